// round 1
// baseline (speedup 1.0000x reference)
#include <cuda_runtime.h>
#include <math.h>

#define Bb 4
#define Tn 1024
#define Cc 1024
#define Hh 16
#define Dd 64

// ---------------- scratch (device globals; zero-initialized at load) ----------------
__device__ float g_xs[(size_t)Bb * Tn * Cc];          // time-shifted input   [B,T,C]
__device__ float g_q[(size_t)Bb * Hh * Tn * Dd];      // [B,H,T,D]
__device__ float g_k[(size_t)Bb * Hh * Tn * Dd];
__device__ float g_v[(size_t)Bb * Hh * Tn * Dd];
__device__ float g_att[(size_t)Bb * Hh * Tn * Tn];    // scores -> softmax -> head-mixed (in place)
__device__ float g_y[(size_t)Bb * Tn * Cc];           // AV output, [B,T,C] with c = h*64+d

// ---------------- 1) time shift ----------------
__global__ __launch_bounds__(256) void timeshift_kernel(const float* __restrict__ x) {
    int idx = blockIdx.x * blockDim.x + threadIdx.x;   // B*T*C = 4M, fits int
    int c = idx & (Cc - 1);
    int t = (idx >> 10) & (Tn - 1);
    int b = idx >> 20;
    float val;
    if (c < Cc / 2) {
        val = (t == 0) ? 0.f : x[((size_t)b * Tn + (t - 1)) * Cc + c];
    } else {
        val = x[((size_t)b * Tn + t) * Cc + c];
    }
    g_xs[idx] = val;
}

// ---------------- 2/7) projection GEMM: out[m,n] = sum_k A[m,k]*W[n,k] + bias[n] ----------------
// which = 0,1,2 : A = g_xs, output -> g_q/g_k/g_v in [B,H,T,D] layout
// which = 3     : A = g_y,  output -> outflat [B,T,C]
__global__ __launch_bounds__(256) void proj_gemm(const float* __restrict__ W,
                                                 const float* __restrict__ bias,
                                                 float* __restrict__ outflat, int which) {
    __shared__ float As[16][68];
    __shared__ float Bs[16][68];
    const float* A = (which == 3) ? g_y : g_xs;
    float* outb = (which == 0) ? g_q : (which == 1) ? g_k : (which == 2) ? g_v : outflat;

    int tid = threadIdx.x;
    int m0 = blockIdx.y * 64, n0 = blockIdx.x * 64;
    int lr = tid >> 2;          // 0..63
    int lc = (tid & 3) * 4;     // 0,4,8,12
    int tx = tid & 15, ty = tid >> 4;
    float acc[4][4] = {};

    for (int k0 = 0; k0 < Cc; k0 += 16) {
        float4 a = *reinterpret_cast<const float4*>(&A[((size_t)(m0 + lr)) * Cc + k0 + lc]);
        float4 w = *reinterpret_cast<const float4*>(&W[((size_t)(n0 + lr)) * Cc + k0 + lc]);
        As[lc + 0][lr] = a.x; As[lc + 1][lr] = a.y; As[lc + 2][lr] = a.z; As[lc + 3][lr] = a.w;
        Bs[lc + 0][lr] = w.x; Bs[lc + 1][lr] = w.y; Bs[lc + 2][lr] = w.z; Bs[lc + 3][lr] = w.w;
        __syncthreads();
#pragma unroll
        for (int k = 0; k < 16; k++) {
            float ra[4], rb[4];
#pragma unroll
            for (int i = 0; i < 4; i++) { ra[i] = As[k][ty * 4 + i]; rb[i] = Bs[k][tx * 4 + i]; }
#pragma unroll
            for (int i = 0; i < 4; i++)
#pragma unroll
                for (int j = 0; j < 4; j++) acc[i][j] = fmaf(ra[i], rb[j], acc[i][j]);
        }
        __syncthreads();
    }

#pragma unroll
    for (int i = 0; i < 4; i++) {
        int m = m0 + ty * 4 + i;
        int b = m >> 10, t = m & 1023;
#pragma unroll
        for (int j = 0; j < 4; j++) {
            int n = n0 + tx * 4 + j;
            float val = acc[i][j] + bias[n];
            if (which == 3) {
                outb[(size_t)m * Cc + n] = val;
            } else {
                int h = n >> 6, d = n & 63;
                outb[(((size_t)(b * Hh + h)) * Tn + t) * Dd + d] = val;
            }
        }
    }
}

// ---------------- 3) scores: S[t,s] = q.k / 8, causal blocks only ----------------
__global__ __launch_bounds__(256) void scores_kernel() {
    int sblk = blockIdx.x, tblk = blockIdx.y, bh = blockIdx.z;
    if (sblk > tblk) return;
    const float* Q  = g_q + (size_t)bh * Tn * Dd;
    const float* Kp = g_k + (size_t)bh * Tn * Dd;
    float* S = g_att + (size_t)bh * Tn * Tn;

    __shared__ float As[16][68];
    __shared__ float Bs[16][68];
    int tid = threadIdx.x;
    int lr = tid >> 2, lc = (tid & 3) * 4;
    int tx = tid & 15, ty = tid >> 4;
    int t0 = tblk * 64, s0 = sblk * 64;
    float acc[4][4] = {};

    for (int k0 = 0; k0 < Dd; k0 += 16) {
        float4 a = *reinterpret_cast<const float4*>(&Q[((size_t)(t0 + lr)) * Dd + k0 + lc]);
        float4 w = *reinterpret_cast<const float4*>(&Kp[((size_t)(s0 + lr)) * Dd + k0 + lc]);
        As[lc + 0][lr] = a.x; As[lc + 1][lr] = a.y; As[lc + 2][lr] = a.z; As[lc + 3][lr] = a.w;
        Bs[lc + 0][lr] = w.x; Bs[lc + 1][lr] = w.y; Bs[lc + 2][lr] = w.z; Bs[lc + 3][lr] = w.w;
        __syncthreads();
#pragma unroll
        for (int k = 0; k < 16; k++) {
            float ra[4], rb[4];
#pragma unroll
            for (int i = 0; i < 4; i++) { ra[i] = As[k][ty * 4 + i]; rb[i] = Bs[k][tx * 4 + i]; }
#pragma unroll
            for (int i = 0; i < 4; i++)
#pragma unroll
                for (int j = 0; j < 4; j++) acc[i][j] = fmaf(ra[i], rb[j], acc[i][j]);
        }
        __syncthreads();
    }
#pragma unroll
    for (int i = 0; i < 4; i++)
#pragma unroll
        for (int j = 0; j < 4; j++)
            S[(size_t)(t0 + ty * 4 + i) * Tn + s0 + tx * 4 + j] = acc[i][j] * 0.125f;
}

// ---------------- 4) row softmax over s<=t, then * time_weighting ----------------
__global__ __launch_bounds__(256) void softmax_tw_kernel(const float* __restrict__ tw) {
    int t = blockIdx.x;
    int bh = blockIdx.y;
    int h = bh & (Hh - 1);
    float* row = g_att + ((size_t)bh * Tn + t) * Tn;
    const float* twr = tw + ((size_t)h * Tn + t) * Tn;
    int n = t + 1;
    int tid = threadIdx.x;
    __shared__ float red[8];

    // max
    float m = -1e30f;
    for (int i = tid; i < n; i += 256) m = fmaxf(m, row[i]);
#pragma unroll
    for (int o = 16; o; o >>= 1) m = fmaxf(m, __shfl_xor_sync(0xffffffffu, m, o));
    if ((tid & 31) == 0) red[tid >> 5] = m;
    __syncthreads();
    float mm = red[0];
#pragma unroll
    for (int i = 1; i < 8; i++) mm = fmaxf(mm, red[i]);
    m = mm;
    __syncthreads();

    // exp + sum
    float s = 0.f;
    for (int i = tid; i < n; i += 256) {
        float e = __expf(row[i] - m);
        row[i] = e;
        s += e;
    }
#pragma unroll
    for (int o = 16; o; o >>= 1) s += __shfl_xor_sync(0xffffffffu, s, o);
    if ((tid & 31) == 0) red[tid >> 5] = s;
    __syncthreads();
    float ss = 0.f;
#pragma unroll
    for (int i = 0; i < 8; i++) ss += red[i];
    float inv = 1.0f / ss;

    // normalize * tw
    for (int i = tid; i < n; i += 256) row[i] = row[i] * inv * twr[i];
}

// ---------------- 5) head mix (1x1 conv over heads), in place ----------------
__global__ __launch_bounds__(256) void headmix_kernel(const float* __restrict__ Mx) {
    int chunk = blockIdx.x;
    int t = blockIdx.y;
    int b = blockIdx.z;
    int s0 = chunk * 256;
    if (s0 > t) return;            // beyond causal region: stays 0 forever
    __shared__ float sm[16][256];
    __shared__ float Ms[256];
    int tid = threadIdx.x;
    Ms[tid] = Mx[tid];             // 16x16 = 256
#pragma unroll
    for (int h = 0; h < Hh; h++)
        sm[h][tid] = g_att[(((size_t)(b * Hh + h)) * Tn + t) * Tn + s0 + tid];
    __syncthreads();
    float vals[16];
#pragma unroll
    for (int h = 0; h < Hh; h++) vals[h] = sm[h][tid];
#pragma unroll
    for (int o = 0; o < Hh; o++) {
        float acc = 0.f;
#pragma unroll
        for (int h = 0; h < Hh; h++) acc = fmaf(Ms[o * 16 + h], vals[h], acc);
        g_att[(((size_t)(b * Hh + o)) * Tn + t) * Tn + s0 + tid] = acc;
    }
}

// ---------------- 6) y = attmix @ v  (causal-guarded), writes [B,T,C] ----------------
__global__ __launch_bounds__(256) void av_kernel() {
    int tblk = blockIdx.x;
    int bo = blockIdx.y;           // b*16 + o
    int b = bo >> 4, o = bo & 15;
    const float* A = g_att + (size_t)bo * Tn * Tn;
    const float* V = g_v + (size_t)bo * Tn * Dd;

    __shared__ float As[16][68];
    __shared__ float Bs[16][68];
    int tid = threadIdx.x;
    int lr = tid >> 2, lc = (tid & 3) * 4;
    int vr = tid >> 4, vc = (tid & 15) * 4;
    int tx = tid & 15, ty = tid >> 4;
    int t0 = tblk * 64;
    float acc[4][4] = {};

    int kmax = t0 + 64;            // s tiles up to and including diagonal block
    for (int s0 = 0; s0 < kmax; s0 += 16) {
        int gt = t0 + lr;
        float4 a = *reinterpret_cast<const float4*>(&A[(size_t)gt * Tn + s0 + lc]);
        As[lc + 0][lr] = (s0 + lc + 0 <= gt) ? a.x : 0.f;
        As[lc + 1][lr] = (s0 + lc + 1 <= gt) ? a.y : 0.f;
        As[lc + 2][lr] = (s0 + lc + 2 <= gt) ? a.z : 0.f;
        As[lc + 3][lr] = (s0 + lc + 3 <= gt) ? a.w : 0.f;
        float4 bv4 = *reinterpret_cast<const float4*>(&V[(size_t)(s0 + vr) * Dd + vc]);
        Bs[vr][vc + 0] = bv4.x; Bs[vr][vc + 1] = bv4.y; Bs[vr][vc + 2] = bv4.z; Bs[vr][vc + 3] = bv4.w;
        __syncthreads();
#pragma unroll
        for (int k = 0; k < 16; k++) {
            float ra[4], rb[4];
#pragma unroll
            for (int i = 0; i < 4; i++) { ra[i] = As[k][ty * 4 + i]; rb[i] = Bs[k][tx * 4 + i]; }
#pragma unroll
            for (int i = 0; i < 4; i++)
#pragma unroll
                for (int j = 0; j < 4; j++) acc[i][j] = fmaf(ra[i], rb[j], acc[i][j]);
        }
        __syncthreads();
    }

#pragma unroll
    for (int i = 0; i < 4; i++) {
        int t = t0 + ty * 4 + i;
#pragma unroll
        for (int j = 0; j < 4; j++) {
            int d = tx * 4 + j;
            g_y[((size_t)(b * Tn + t)) * Cc + o * 64 + d] = acc[i][j];
        }
    }
}

// ---------------- host launch ----------------
extern "C" void kernel_launch(void* const* d_in, const int* in_sizes, int n_in,
                              void* d_out, int out_size) {
    const float* x  = (const float*)d_in[0];
    const float* Wq = (const float*)d_in[1];
    const float* bq = (const float*)d_in[2];
    const float* Wk = (const float*)d_in[3];
    const float* bk = (const float*)d_in[4];
    const float* Wv = (const float*)d_in[5];
    const float* bv = (const float*)d_in[6];
    const float* tw = (const float*)d_in[7];
    const float* hm = (const float*)d_in[8];
    const float* Wp = (const float*)d_in[9];
    const float* bp = (const float*)d_in[10];
    float* out = (float*)d_out;

    timeshift_kernel<<<(Bb * Tn * Cc) / 256, 256>>>(x);

    dim3 gproj(Cc / 64, (Bb * Tn) / 64);
    proj_gemm<<<gproj, 256>>>(Wq, bq, nullptr, 0);
    proj_gemm<<<gproj, 256>>>(Wk, bk, nullptr, 1);
    proj_gemm<<<gproj, 256>>>(Wv, bv, nullptr, 2);

    dim3 gs(Tn / 64, Tn / 64, Bb * Hh);
    scores_kernel<<<gs, 256>>>();

    dim3 gsm(Tn, Bb * Hh);
    softmax_tw_kernel<<<gsm, 256>>>(tw);

    dim3 ghm(Tn / 256, Tn, Bb);
    headmix_kernel<<<ghm, 256>>>(hm);

    dim3 gav(Tn / 64, Bb * Hh);
    av_kernel<<<gav, 256>>>();

    proj_gemm<<<gproj, 256>>>(Wp, bp, out, 3);
}

// round 3
// speedup vs baseline: 1.7655x; 1.7655x over previous
#include <cuda_runtime.h>
#include <cuda_bf16.h>
#include <math.h>
#include <cstdint>

#define Bb 4
#define Tn 1024
#define Cc 1024
#define Hh 16
#define Dd 64
#define NELEM ((size_t)Bb * Tn * Cc)   // 4M

// ---------------- scratch (device globals) ----------------
__device__ float g_q[(size_t)Bb * Hh * Tn * Dd];      // [B,H,T,D]
__device__ float g_k[(size_t)Bb * Hh * Tn * Dd];
__device__ float g_v[(size_t)Bb * Hh * Tn * Dd];
__device__ float g_att[(size_t)Bb * Hh * Tn * Tn];    // scores -> softmax -> head-mixed (in place)

__device__ __nv_bfloat16 g_xs_h[NELEM];               // time-shifted input, bf16 hi/lo
__device__ __nv_bfloat16 g_xs_l[NELEM];
__device__ __nv_bfloat16 g_y_h[NELEM];                // AV output [B,T,C] (c = h*64+d), hi/lo
__device__ __nv_bfloat16 g_y_l[NELEM];
__device__ __nv_bfloat16 g_wh[4 * (size_t)Cc * Cc];   // weights q,k,v,p  hi
__device__ __nv_bfloat16 g_wl[4 * (size_t)Cc * Cc];   // weights q,k,v,p  lo

// ================= helpers =================
__device__ __forceinline__ uint32_t smem_to_u32(const void* p) {
    uint32_t a;
    asm("{ .reg .u64 t; cvta.to.shared.u64 t, %1; cvt.u32.u64 %0, t; }" : "=r"(a) : "l"(p));
    return a;
}
#define CP16(dst, src) \
    asm volatile("cp.async.cg.shared.global [%0], [%1], 16;" :: "r"(dst), "l"(src) : "memory")
#define CP_COMMIT() asm volatile("cp.async.commit_group;" ::: "memory")
#define CP_WAIT0() asm volatile("cp.async.wait_group 0;" ::: "memory")
#define CP_WAIT1() asm volatile("cp.async.wait_group 1;" ::: "memory")

__device__ __forceinline__ void ldsm4(uint32_t* r, uint32_t addr) {
    asm volatile("ldmatrix.sync.aligned.m8n8.x4.shared.b16 {%0,%1,%2,%3}, [%4];"
                 : "=r"(r[0]), "=r"(r[1]), "=r"(r[2]), "=r"(r[3]) : "r"(addr));
}
__device__ __forceinline__ void ldsm2(uint32_t* r, uint32_t addr) {
    asm volatile("ldmatrix.sync.aligned.m8n8.x2.shared.b16 {%0,%1}, [%2];"
                 : "=r"(r[0]), "=r"(r[1]) : "r"(addr));
}
__device__ __forceinline__ void mma16816(float* c, const uint32_t* a, const uint32_t* b) {
    asm volatile("mma.sync.aligned.m16n8k16.row.col.f32.bf16.bf16.f32 "
                 "{%0,%1,%2,%3}, {%4,%5,%6,%7}, {%8,%9}, {%0,%1,%2,%3};"
                 : "+f"(c[0]), "+f"(c[1]), "+f"(c[2]), "+f"(c[3])
                 : "r"(a[0]), "r"(a[1]), "r"(a[2]), "r"(a[3]), "r"(b[0]), "r"(b[1]));
}

__device__ __forceinline__ void split_store(__nv_bfloat16* ph, __nv_bfloat16* pl, size_t idx, float v) {
    __nv_bfloat16 h = __float2bfloat16_rn(v);
    ph[idx] = h;
    pl[idx] = __float2bfloat16_rn(v - __bfloat162float(h));
}

// ---------------- 1) time shift -> bf16 hi/lo ----------------
__global__ __launch_bounds__(256) void timeshift_kernel(const float* __restrict__ x) {
    int idx = blockIdx.x * blockDim.x + threadIdx.x;
    int c = idx & (Cc - 1);
    int t = (idx >> 10) & (Tn - 1);
    int b = idx >> 20;
    float val;
    if (c < Cc / 2) {
        val = (t == 0) ? 0.f : x[((size_t)b * Tn + (t - 1)) * Cc + c];
    } else {
        val = x[((size_t)b * Tn + t) * Cc + c];
    }
    split_store(g_xs_h, g_xs_l, idx, val);
}

// ---------------- 1b) weight conversion -> bf16 hi/lo ----------------
__global__ __launch_bounds__(256) void convert_w_kernel(const float* __restrict__ Wq,
                                                        const float* __restrict__ Wk,
                                                        const float* __restrict__ Wv,
                                                        const float* __restrict__ Wp) {
    size_t idx = (size_t)blockIdx.x * blockDim.x + threadIdx.x;   // 0 .. 4*C*C-1
    int which = (int)(idx >> 20);
    size_t off = idx & ((size_t)Cc * Cc - 1);
    const float* W = (which == 0) ? Wq : (which == 1) ? Wk : (which == 2) ? Wv : Wp;
    split_store(g_wh, g_wl, idx, W[off]);
}

// ================= 2/7) bf16-split mma.sync projection GEMM =================
// out[m,n] = sum_k A[m,k]*W[n,k] + bias[n];   A,W pre-split into bf16 hi/lo.
// CTA tile 128x128, BK=32, 8 warps, warp tile 64x32, cp.async double buffer.
// smem per stage: Ah(8K) Al(8K) Wh(8K) Wl(8K) = 32KB; 2 stages = 64KB dynamic.
#define STAGE_BYTES 32768
#define PROJ_SMEM (2 * STAGE_BYTES)

__global__ __launch_bounds__(256) void proj_gemm_mma(const float* __restrict__ bias,
                                                     float* __restrict__ outflat, int which) {
    extern __shared__ char smem[];
    uint32_t sbase = smem_to_u32(smem);
    const __nv_bfloat16* gAh = (which == 3) ? g_y_h : g_xs_h;
    const __nv_bfloat16* gAl = (which == 3) ? g_y_l : g_xs_l;
    const __nv_bfloat16* gWh = g_wh + (size_t)which * Cc * Cc;
    const __nv_bfloat16* gWl = g_wl + (size_t)which * Cc * Cc;
    float* outb = (which == 0) ? g_q : (which == 1) ? g_k : (which == 2) ? g_v : outflat;

    int tid = threadIdx.x, lane = tid & 31, wid = tid >> 5;
    int warp_m = wid & 1, warp_n = wid >> 1;
    int m0 = blockIdx.y * 128, n0 = blockIdx.x * 128;

    // cp.async mapping: 512 x 16B per array per stage; thread -> 2 rows
    int rtid = tid >> 2;       // 0..63
    int ctid = tid & 3;        // 16B chunk within 64B row

    // ldmatrix lane geometry
    int a_row_off = (lane & 7) + ((lane >> 3) & 1) * 8;
    int a_chunk = lane >> 4;            // 0/1 (k 8-col group)
    int b_row_off = lane & 7;
    int b_chunk = (lane >> 3) & 1;

    uint32_t aBase[4], aSw[4], bBase[4], bSw[4];
#pragma unroll
    for (int mi = 0; mi < 4; mi++) {
        int r = warp_m * 64 + mi * 16 + a_row_off;
        aBase[mi] = (uint32_t)(r * 64);
        aSw[mi] = (uint32_t)((r >> 1) & 3);
    }
#pragma unroll
    for (int ni = 0; ni < 4; ni++) {
        int r = warp_n * 32 + ni * 8 + b_row_off;
        bBase[ni] = (uint32_t)(r * 64);
        bSw[ni] = (uint32_t)((r >> 1) & 3);
    }

    float acc[4][4][4];
#pragma unroll
    for (int mi = 0; mi < 4; mi++)
#pragma unroll
        for (int ni = 0; ni < 4; ni++)
#pragma unroll
            for (int j = 0; j < 4; j++) acc[mi][ni][j] = 0.f;

    auto issue = [&](int chunk, int stage) {
        int k0 = chunk * 32;
        uint32_t sb = sbase + (uint32_t)stage * STAGE_BYTES;
#pragma unroll
        for (int j = 0; j < 2; j++) {
            int row = rtid + j * 64;
            uint32_t dof = (uint32_t)(row * 64 + ((ctid ^ ((row >> 1) & 3)) << 4));
            size_t ga = (size_t)(m0 + row) * Cc + k0 + ctid * 8;
            size_t gw = (size_t)(n0 + row) * Cc + k0 + ctid * 8;
            CP16(sb + dof,         gAh + ga);
            CP16(sb + 8192 + dof,  gAl + ga);
            CP16(sb + 16384 + dof, gWh + gw);
            CP16(sb + 24576 + dof, gWl + gw);
        }
    };

    auto compute = [&](int stage) {
        uint32_t sb = sbase + (uint32_t)stage * STAGE_BYTES;
#pragma unroll
        for (int ks = 0; ks < 2; ks++) {
            uint32_t aH[4][4], aL[4][4], bH[4][2], bL[4][2];
#pragma unroll
            for (int mi = 0; mi < 4; mi++) {
                uint32_t off = aBase[mi] + ((((uint32_t)(ks * 2) + a_chunk) ^ aSw[mi]) << 4);
                ldsm4(aH[mi], sb + off);
                ldsm4(aL[mi], sb + 8192 + off);
            }
#pragma unroll
            for (int ni = 0; ni < 4; ni++) {
                uint32_t off = bBase[ni] + ((((uint32_t)(ks * 2) + b_chunk) ^ bSw[ni]) << 4);
                ldsm2(bH[ni], sb + 16384 + off);
                ldsm2(bL[ni], sb + 24576 + off);
            }
#pragma unroll
            for (int mi = 0; mi < 4; mi++)
#pragma unroll
                for (int ni = 0; ni < 4; ni++) {
                    mma16816(acc[mi][ni], aH[mi], bH[ni]);
                    mma16816(acc[mi][ni], aH[mi], bL[ni]);
                    mma16816(acc[mi][ni], aL[mi], bH[ni]);
                }
        }
    };

    const int NCH = Cc / 32;   // 32
    issue(0, 0);
    CP_COMMIT();
#pragma unroll 1
    for (int c = 0; c < NCH; c++) {
        if (c + 1 < NCH) {
            issue(c + 1, (c + 1) & 1);
            CP_COMMIT();
            CP_WAIT1();
        } else {
            CP_WAIT0();
        }
        __syncthreads();
        compute(c & 1);
        __syncthreads();
    }

    // epilogue
    int r4 = lane >> 2;
    int cp2 = (lane & 3) * 2;
#pragma unroll
    for (int ni = 0; ni < 4; ni++) {
        int n = n0 + warp_n * 32 + ni * 8 + cp2;
        float b0 = bias[n], b1 = bias[n + 1];
#pragma unroll
        for (int mi = 0; mi < 4; mi++) {
            int mA = m0 + warp_m * 64 + mi * 16 + r4;
            float2 v0 = make_float2(acc[mi][ni][0] + b0, acc[mi][ni][1] + b1);
            float2 v1 = make_float2(acc[mi][ni][2] + b0, acc[mi][ni][3] + b1);
            if (which == 3) {
                *reinterpret_cast<float2*>(&outflat[(size_t)mA * Cc + n]) = v0;
                *reinterpret_cast<float2*>(&outflat[(size_t)(mA + 8) * Cc + n]) = v1;
            } else {
                int h = n >> 6, d = n & 63;
                int b_ = mA >> 10, t = mA & 1023;
                *reinterpret_cast<float2*>(&outb[(((size_t)(b_ * Hh + h)) * Tn + t) * Dd + d]) = v0;
                int m2 = mA + 8;
                int b2 = m2 >> 10, t2 = m2 & 1023;
                *reinterpret_cast<float2*>(&outb[(((size_t)(b2 * Hh + h)) * Tn + t2) * Dd + d]) = v1;
            }
        }
    }
}

// ---------------- 3) scores: S[t,s] = q.k / 8, causal blocks only ----------------
__global__ __launch_bounds__(256) void scores_kernel() {
    int sblk = blockIdx.x, tblk = blockIdx.y, bh = blockIdx.z;
    if (sblk > tblk) return;
    const float* Q  = g_q + (size_t)bh * Tn * Dd;
    const float* Kp = g_k + (size_t)bh * Tn * Dd;
    float* S = g_att + (size_t)bh * Tn * Tn;

    __shared__ float As[16][68];
    __shared__ float Bs[16][68];
    int tid = threadIdx.x;
    int lr = tid >> 2, lc = (tid & 3) * 4;
    int tx = tid & 15, ty = tid >> 4;
    int t0 = tblk * 64, s0 = sblk * 64;
    float acc[4][4] = {};

    for (int k0 = 0; k0 < Dd; k0 += 16) {
        float4 a = *reinterpret_cast<const float4*>(&Q[((size_t)(t0 + lr)) * Dd + k0 + lc]);
        float4 w = *reinterpret_cast<const float4*>(&Kp[((size_t)(s0 + lr)) * Dd + k0 + lc]);
        As[lc + 0][lr] = a.x; As[lc + 1][lr] = a.y; As[lc + 2][lr] = a.z; As[lc + 3][lr] = a.w;
        Bs[lc + 0][lr] = w.x; Bs[lc + 1][lr] = w.y; Bs[lc + 2][lr] = w.z; Bs[lc + 3][lr] = w.w;
        __syncthreads();
#pragma unroll
        for (int k = 0; k < 16; k++) {
            float ra[4], rb[4];
#pragma unroll
            for (int i = 0; i < 4; i++) { ra[i] = As[k][ty * 4 + i]; rb[i] = Bs[k][tx * 4 + i]; }
#pragma unroll
            for (int i = 0; i < 4; i++)
#pragma unroll
                for (int j = 0; j < 4; j++) acc[i][j] = fmaf(ra[i], rb[j], acc[i][j]);
        }
        __syncthreads();
    }
#pragma unroll
    for (int i = 0; i < 4; i++)
#pragma unroll
        for (int j = 0; j < 4; j++)
            S[(size_t)(t0 + ty * 4 + i) * Tn + s0 + tx * 4 + j] = acc[i][j] * 0.125f;
}

// ---------------- 4) row softmax over s<=t, then * time_weighting ----------------
__global__ __launch_bounds__(256) void softmax_tw_kernel(const float* __restrict__ tw) {
    int t = blockIdx.x;
    int bh = blockIdx.y;
    int h = bh & (Hh - 1);
    float* row = g_att + ((size_t)bh * Tn + t) * Tn;
    const float* twr = tw + ((size_t)h * Tn + t) * Tn;
    int n = t + 1;
    int tid = threadIdx.x;
    __shared__ float red[8];

    float m = -1e30f;
    for (int i = tid; i < n; i += 256) m = fmaxf(m, row[i]);
#pragma unroll
    for (int o = 16; o; o >>= 1) m = fmaxf(m, __shfl_xor_sync(0xffffffffu, m, o));
    if ((tid & 31) == 0) red[tid >> 5] = m;
    __syncthreads();
    float mm = red[0];
#pragma unroll
    for (int i = 1; i < 8; i++) mm = fmaxf(mm, red[i]);
    m = mm;
    __syncthreads();

    float s = 0.f;
    for (int i = tid; i < n; i += 256) {
        float e = __expf(row[i] - m);
        row[i] = e;
        s += e;
    }
#pragma unroll
    for (int o = 16; o; o >>= 1) s += __shfl_xor_sync(0xffffffffu, s, o);
    if ((tid & 31) == 0) red[tid >> 5] = s;
    __syncthreads();
    float ss = 0.f;
#pragma unroll
    for (int i = 0; i < 8; i++) ss += red[i];
    float inv = 1.0f / ss;

    for (int i = tid; i < n; i += 256) row[i] = row[i] * inv * twr[i];
}

// ---------------- 5) head mix (1x1 conv over heads), in place ----------------
__global__ __launch_bounds__(256) void headmix_kernel(const float* __restrict__ Mx) {
    int chunk = blockIdx.x;
    int t = blockIdx.y;
    int b = blockIdx.z;
    int s0 = chunk * 256;
    if (s0 > t) return;
    __shared__ float sm[16][256];
    __shared__ float Ms[256];
    int tid = threadIdx.x;
    Ms[tid] = Mx[tid];
#pragma unroll
    for (int h = 0; h < Hh; h++)
        sm[h][tid] = g_att[(((size_t)(b * Hh + h)) * Tn + t) * Tn + s0 + tid];
    __syncthreads();
    float vals[16];
#pragma unroll
    for (int h = 0; h < Hh; h++) vals[h] = sm[h][tid];
#pragma unroll
    for (int o = 0; o < Hh; o++) {
        float acc = 0.f;
#pragma unroll
        for (int h = 0; h < Hh; h++) acc = fmaf(Ms[o * 16 + h], vals[h], acc);
        g_att[(((size_t)(b * Hh + o)) * Tn + t) * Tn + s0 + tid] = acc;
    }
}

// ---------------- 6) y = attmix @ v  (causal-guarded), writes bf16 hi/lo [B,T,C] ----------------
__global__ __launch_bounds__(256) void av_kernel() {
    int tblk = blockIdx.x;
    int bo = blockIdx.y;
    int b = bo >> 4, o = bo & 15;
    const float* A = g_att + (size_t)bo * Tn * Tn;
    const float* V = g_v + (size_t)bo * Tn * Dd;

    __shared__ float As[16][68];
    __shared__ float Bs[16][68];
    int tid = threadIdx.x;
    int lr = tid >> 2, lc = (tid & 3) * 4;
    int vr = tid >> 4, vc = (tid & 15) * 4;
    int tx = tid & 15, ty = tid >> 4;
    int t0 = tblk * 64;
    float acc[4][4] = {};

    int kmax = t0 + 64;
    for (int s0 = 0; s0 < kmax; s0 += 16) {
        int gt = t0 + lr;
        float4 a = *reinterpret_cast<const float4*>(&A[(size_t)gt * Tn + s0 + lc]);
        As[lc + 0][lr] = (s0 + lc + 0 <= gt) ? a.x : 0.f;
        As[lc + 1][lr] = (s0 + lc + 1 <= gt) ? a.y : 0.f;
        As[lc + 2][lr] = (s0 + lc + 2 <= gt) ? a.z : 0.f;
        As[lc + 3][lr] = (s0 + lc + 3 <= gt) ? a.w : 0.f;
        float4 bv4 = *reinterpret_cast<const float4*>(&V[(size_t)(s0 + vr) * Dd + vc]);
        Bs[vr][vc + 0] = bv4.x; Bs[vr][vc + 1] = bv4.y; Bs[vr][vc + 2] = bv4.z; Bs[vr][vc + 3] = bv4.w;
        __syncthreads();
#pragma unroll
        for (int k = 0; k < 16; k++) {
            float ra[4], rb[4];
#pragma unroll
            for (int i = 0; i < 4; i++) { ra[i] = As[k][ty * 4 + i]; rb[i] = Bs[k][tx * 4 + i]; }
#pragma unroll
            for (int i = 0; i < 4; i++)
#pragma unroll
                for (int j = 0; j < 4; j++) acc[i][j] = fmaf(ra[i], rb[j], acc[i][j]);
        }
        __syncthreads();
    }

#pragma unroll
    for (int i = 0; i < 4; i++) {
        int t = t0 + ty * 4 + i;
#pragma unroll
        for (int j = 0; j < 4; j++) {
            int d = tx * 4 + j;
            size_t idx = ((size_t)(b * Tn + t)) * Cc + o * 64 + d;
            split_store(g_y_h, g_y_l, idx, acc[i][j]);
        }
    }
}

// ---------------- host launch ----------------
extern "C" void kernel_launch(void* const* d_in, const int* in_sizes, int n_in,
                              void* d_out, int out_size) {
    const float* x  = (const float*)d_in[0];
    const float* Wq = (const float*)d_in[1];
    const float* bq = (const float*)d_in[2];
    const float* Wk = (const float*)d_in[3];
    const float* bk = (const float*)d_in[4];
    const float* Wv = (const float*)d_in[5];
    const float* bv = (const float*)d_in[6];
    const float* tw = (const float*)d_in[7];
    const float* hm = (const float*)d_in[8];
    const float* Wp = (const float*)d_in[9];
    const float* bp = (const float*)d_in[10];
    float* out = (float*)d_out;

    static int smem_set = 0;
    if (!smem_set) {
        cudaFuncSetAttribute(proj_gemm_mma, cudaFuncAttributeMaxDynamicSharedMemorySize, PROJ_SMEM);
        smem_set = 1;
    }

    timeshift_kernel<<<(Bb * Tn * Cc) / 256, 256>>>(x);
    convert_w_kernel<<<(4 * Cc * Cc) / 256, 256>>>(Wq, Wk, Wv, Wp);

    dim3 gproj(Cc / 128, (Bb * Tn) / 128);  // (8, 32)
    proj_gemm_mma<<<gproj, 256, PROJ_SMEM>>>(bq, nullptr, 0);
    proj_gemm_mma<<<gproj, 256, PROJ_SMEM>>>(bk, nullptr, 1);
    proj_gemm_mma<<<gproj, 256, PROJ_SMEM>>>(bv, nullptr, 2);

    dim3 gs(Tn / 64, Tn / 64, Bb * Hh);
    scores_kernel<<<gs, 256>>>();

    dim3 gsm(Tn, Bb * Hh);
    softmax_tw_kernel<<<gsm, 256>>>(tw);

    dim3 ghm(Tn / 256, Tn, Bb);
    headmix_kernel<<<ghm, 256>>>(hm);

    dim3 gav(Tn / 64, Bb * Hh);
    av_kernel<<<gav, 256>>>();

    proj_gemm_mma<<<gproj, 256, PROJ_SMEM>>>(bp, out, 3);
}